// round 1
// baseline (speedup 1.0000x reference)
#include <cuda_runtime.h>
#include <math.h>

#define N_NODES 50000
#define N_EDGES 800000
#define IN_DIM  512
#define HID     256
#define LAT     64
#define SLOPE   0.2f

// ---------------- scratch (no allocations allowed) ----------------
__device__ float g_h1 [(size_t)N_NODES * HID];
__device__ float g_h1o[(size_t)N_NODES * HID];
__device__ float g_h3 [(size_t)N_NODES * HID];
__device__ float g_h3o[(size_t)N_NODES * HID];
__device__ float g_asrc[N_NODES];
__device__ float g_adst[N_NODES];
__device__ float g_alpha[N_EDGES];     // softmax-normalized attention, CSR order
__device__ int   g_deg[N_NODES];
__device__ int   g_off[N_NODES + 1];
__device__ int   g_cursor[N_NODES];
__device__ int   g_ssrc[N_EDGES];      // src node per CSR-sorted edge

// ---------------- CSR build ----------------
__global__ void k_zero_deg() {
    int i = blockIdx.x * blockDim.x + threadIdx.x;
    if (i < N_NODES) g_deg[i] = 0;
}

__global__ void k_count(const int* __restrict__ dst) {
    int e = blockIdx.x * blockDim.x + threadIdx.x;
    if (e < N_EDGES) atomicAdd(&g_deg[dst[e]], 1);
}

__global__ void k_scan() {
    __shared__ int buf[1024];
    __shared__ int carry;
    int t = threadIdx.x;
    if (t == 0) carry = 0;
    __syncthreads();
    for (int base = 0; base < N_NODES; base += 1024) {
        int idx = base + t;
        int v = (idx < N_NODES) ? g_deg[idx] : 0;
        buf[t] = v;
        __syncthreads();
        for (int o = 1; o < 1024; o <<= 1) {
            int x = (t >= o) ? buf[t - o] : 0;
            __syncthreads();
            buf[t] += x;
            __syncthreads();
        }
        int excl = buf[t] - v;
        if (idx < N_NODES) { g_off[idx] = carry + excl; g_cursor[idx] = carry + excl; }
        int total = buf[1023];
        __syncthreads();
        if (t == 0) carry += total;
        __syncthreads();
    }
    if (t == 0) g_off[N_NODES] = carry;
}

__global__ void k_fill(const int* __restrict__ src, const int* __restrict__ dst) {
    int e = blockIdx.x * blockDim.x + threadIdx.x;
    if (e < N_EDGES) {
        int d = dst[e];
        int p = atomicAdd(&g_cursor[d], 1);
        g_ssrc[p] = src[e];
    }
}

// ---------------- attention scalars ----------------
// a_src[n] = dot(h1[n], att_src); a_dst[n] = dot(h1[n], att_dst). One warp/node.
__global__ void k_dots(const float* __restrict__ att_src, const float* __restrict__ att_dst) {
    int w = (blockIdx.x * blockDim.x + threadIdx.x) >> 5;
    int lane = threadIdx.x & 31;
    if (w >= N_NODES) return;
    const float4* row = (const float4*)(g_h1 + (size_t)w * HID);
    const float4* as4 = (const float4*)att_src;
    const float4* ad4 = (const float4*)att_dst;
    float s = 0.f, d = 0.f;
#pragma unroll
    for (int i = 0; i < 2; i++) {
        float4 h = row[lane + 32 * i];
        float4 a = as4[lane + 32 * i];
        float4 b = ad4[lane + 32 * i];
        s += h.x * a.x + h.y * a.y + h.z * a.z + h.w * a.w;
        d += h.x * b.x + h.y * b.y + h.z * b.z + h.w * b.w;
    }
    for (int o = 16; o; o >>= 1) {
        s += __shfl_xor_sync(0xffffffffu, s, o);
        d += __shfl_xor_sync(0xffffffffu, d, o);
    }
    if (lane == 0) { g_asrc[w] = s; g_adst[w] = d; }
}

// Per-dst segment softmax of leakyrelu(a_src[src] + a_dst[dst]). One warp/node.
__global__ void k_softmax() {
    int w = (blockIdx.x * blockDim.x + threadIdx.x) >> 5;
    int lane = threadIdx.x & 31;
    if (w >= N_NODES) return;
    int lo = g_off[w], hi = g_off[w + 1];
    if (lo == hi) return;
    float ad = g_adst[w];
    float m = -INFINITY;
    for (int p = lo + lane; p < hi; p += 32) {
        float e = g_asrc[g_ssrc[p]] + ad;
        e = e > 0.f ? e : SLOPE * e;
        m = fmaxf(m, e);
    }
    for (int o = 16; o; o >>= 1) m = fmaxf(m, __shfl_xor_sync(0xffffffffu, m, o));
    float sum = 0.f;
    for (int p = lo + lane; p < hi; p += 32) {
        float e = g_asrc[g_ssrc[p]] + ad;
        e = e > 0.f ? e : SLOPE * e;
        float ex = expf(e - m);
        g_alpha[p] = ex;
        sum += ex;
    }
    for (int o = 16; o; o >>= 1) sum += __shfl_xor_sync(0xffffffffu, sum, o);
    float inv = 1.f / sum;
    for (int p = lo + lane; p < hi; p += 32) g_alpha[p] *= inv;
}

// out[n] = act( sum_{p in seg(n)} alpha[p] * h[ssrc[p]] ).  One warp/node, 256 ch.
// ACT: 0 = ELU, 1 = ReLU
template <int ACT>
__global__ void k_agg(const float* __restrict__ h, float* __restrict__ out) {
    int w = (blockIdx.x * blockDim.x + threadIdx.x) >> 5;
    int lane = threadIdx.x & 31;
    if (w >= N_NODES) return;
    int lo = g_off[w], hi = g_off[w + 1];
    float4 acc0 = make_float4(0.f, 0.f, 0.f, 0.f);
    float4 acc1 = make_float4(0.f, 0.f, 0.f, 0.f);
    for (int p = lo; p < hi; p++) {
        float a = g_alpha[p];
        const float4* row = (const float4*)(h + (size_t)g_ssrc[p] * HID);
        float4 v0 = row[lane];
        float4 v1 = row[lane + 32];
        acc0.x += a * v0.x; acc0.y += a * v0.y; acc0.z += a * v0.z; acc0.w += a * v0.w;
        acc1.x += a * v1.x; acc1.y += a * v1.y; acc1.z += a * v1.z; acc1.w += a * v1.w;
    }
    float v[8] = {acc0.x, acc0.y, acc0.z, acc0.w, acc1.x, acc1.y, acc1.z, acc1.w};
#pragma unroll
    for (int i = 0; i < 8; i++) {
        if (ACT == 0) v[i] = v[i] > 0.f ? v[i] : (expf(v[i]) - 1.f);
        else          v[i] = v[i] > 0.f ? v[i] : 0.f;
    }
    float4* o4 = (float4*)(out + (size_t)w * HID);
    o4[lane]      = make_float4(v[0], v[1], v[2], v[3]);
    o4[lane + 32] = make_float4(v[4], v[5], v[6], v[7]);
}

// ---------------- SGEMM: C[M,N] = A[M,K] @ B  (B row-major [K,N], or [N,K] if TRANSB)
// BM=128, BN=64, BK=8, 256 threads, 8x4 microtile
template <bool TRANSB>
__global__ void sgemm(const float* __restrict__ A, const float* __restrict__ B,
                      float* __restrict__ C, int M, int N, int K) {
    __shared__ float As[8][128];
    __shared__ float Bs[8][64];
    int t  = threadIdx.x;
    int tx = t & 15;      // 0..15 (n groups of 4)
    int ty = t >> 4;      // 0..15 (m groups of 8)
    int mb = blockIdx.y * 128;
    int nb = blockIdx.x * 64;

    float acc[8][4];
#pragma unroll
    for (int i = 0; i < 8; i++)
#pragma unroll
        for (int j = 0; j < 4; j++) acc[i][j] = 0.f;

    int m_l = t >> 1;            // 0..127
    int kq  = (t & 1) * 4;       // 0 or 4
    bool mok = (mb + m_l) < M;

    for (int k0 = 0; k0 < K; k0 += 8) {
        float4 av = make_float4(0.f, 0.f, 0.f, 0.f);
        if (mok) av = *(const float4*)(A + (size_t)(mb + m_l) * K + k0 + kq);
        As[kq + 0][m_l] = av.x; As[kq + 1][m_l] = av.y;
        As[kq + 2][m_l] = av.z; As[kq + 3][m_l] = av.w;

        if (t < 128) {
            if (!TRANSB) {
                int kk = t >> 4;              // 0..7
                int nq = (t & 15) * 4;        // 0..60
                float4 bv = *(const float4*)(B + (size_t)(k0 + kk) * N + nb + nq);
                *(float4*)&Bs[kk][nq] = bv;
            } else {
                int nn  = t >> 1;             // 0..63
                int kq2 = (t & 1) * 4;
                float4 bv = *(const float4*)(B + (size_t)(nb + nn) * K + k0 + kq2);
                Bs[kq2 + 0][nn] = bv.x; Bs[kq2 + 1][nn] = bv.y;
                Bs[kq2 + 2][nn] = bv.z; Bs[kq2 + 3][nn] = bv.w;
            }
        }
        __syncthreads();

#pragma unroll
        for (int k = 0; k < 8; k++) {
            float4 a0 = *(const float4*)&As[k][ty * 8];
            float4 a1 = *(const float4*)&As[k][ty * 8 + 4];
            float4 b0 = *(const float4*)&Bs[k][tx * 4];
            float a[8] = {a0.x, a0.y, a0.z, a0.w, a1.x, a1.y, a1.z, a1.w};
            float b[4] = {b0.x, b0.y, b0.z, b0.w};
#pragma unroll
            for (int i = 0; i < 8; i++)
#pragma unroll
                for (int j = 0; j < 4; j++) acc[i][j] += a[i] * b[j];
        }
        __syncthreads();
    }

#pragma unroll
    for (int i = 0; i < 8; i++) {
        int m = mb + ty * 8 + i;
        if (m < M) {
            *(float4*)(C + (size_t)m * N + nb + tx * 4) =
                make_float4(acc[i][0], acc[i][1], acc[i][2], acc[i][3]);
        }
    }
}

// ---------------- launch ----------------
extern "C" void kernel_launch(void* const* d_in, const int* in_sizes, int n_in,
                              void* d_out, int out_size) {
    const float* x        = (const float*)d_in[0];
    const int*   ei       = (const int*)d_in[1];
    const float* W1       = (const float*)d_in[2];
    const float* W2       = (const float*)d_in[3];
    const float* att_src1 = (const float*)d_in[4];
    const float* att_dst1 = (const float*)d_in[5];

    float* latent = (float*)d_out;                               // [N, LAT]
    float* recon  = latent + (size_t)N_NODES * LAT;              // [N, IN_DIM]
    const int* src = ei;
    const int* dst = ei + N_EDGES;

    float *h1, *h1o, *h3, *h3o;
    cudaGetSymbolAddress((void**)&h1,  g_h1);
    cudaGetSymbolAddress((void**)&h1o, g_h1o);
    cudaGetSymbolAddress((void**)&h3,  g_h3);
    cudaGetSymbolAddress((void**)&h3o, g_h3o);

    const int EB = (N_EDGES + 255) / 256;
    const int NB = (N_NODES + 255) / 256;
    const int WB = (N_NODES * 32 + 255) / 256;   // warp-per-node kernels
    const int MT = (N_NODES + 127) / 128;        // gemm M tiles

    // CSR build
    k_zero_deg<<<NB, 256>>>();
    k_count<<<EB, 256>>>(dst);
    k_scan<<<1, 1024>>>();
    k_fill<<<EB, 256>>>(src, dst);

    // encoder GAT1
    sgemm<false><<<dim3(HID / 64, MT), 256>>>(x, W1, h1, N_NODES, HID, IN_DIM);
    k_dots<<<WB, 256>>>(att_src1, att_dst1);
    k_softmax<<<WB, 256>>>();
    k_agg<0><<<WB, 256>>>(h1, h1o);                              // ELU

    // encoder GAT2 (no propagation): latent = h1o @ W2
    sgemm<false><<<dim3(LAT / 64, MT), 256>>>(h1o, W2, latent, N_NODES, LAT, HID);

    // decoder GAT1: h3 = latent @ W2^T, attend with tied alpha, ReLU
    sgemm<true><<<dim3(HID / 64, MT), 256>>>(latent, W2, h3, N_NODES, HID, LAT);
    k_agg<1><<<WB, 256>>>(h3, h3o);                              // ReLU

    // decoder GAT2: recon = h3o @ W1^T
    sgemm<true><<<dim3(IN_DIM / 64, MT), 256>>>(h3o, W1, recon, N_NODES, IN_DIM, HID);
}

// round 2
// speedup vs baseline: 1.7089x; 1.7089x over previous
#include <cuda_runtime.h>
#include <math.h>
#include <stdint.h>

#define N_NODES 50000
#define N_EDGES 800000
#define IN_DIM  512
#define HID     256
#define LAT     64
#define SLOPE   0.2f

// ---------------- scratch (no allocations allowed) ----------------
__device__ float g_h1 [(size_t)N_NODES * HID];
__device__ float g_h1o[(size_t)N_NODES * HID];
__device__ float g_h3 [(size_t)N_NODES * HID];
__device__ float g_h3o[(size_t)N_NODES * HID];
__device__ float g_asrc[N_NODES];
__device__ float g_adst[N_NODES];
__device__ float g_alpha[N_EDGES];     // softmax-normalized attention, CSR order
__device__ int   g_deg[N_NODES];
__device__ int   g_off[N_NODES + 1];
__device__ int   g_cursor[N_NODES];
__device__ int   g_ssrc[N_EDGES];      // src node per CSR-sorted edge

// ---------------- CSR build ----------------
__global__ void k_zero_deg() {
    int i = blockIdx.x * blockDim.x + threadIdx.x;
    if (i < N_NODES) g_deg[i] = 0;
}

__global__ void k_count(const int* __restrict__ dst) {
    int e = blockIdx.x * blockDim.x + threadIdx.x;
    if (e < N_EDGES) atomicAdd(&g_deg[dst[e]], 1);
}

__global__ void k_scan() {
    __shared__ int buf[1024];
    __shared__ int carry;
    int t = threadIdx.x;
    if (t == 0) carry = 0;
    __syncthreads();
    for (int base = 0; base < N_NODES; base += 1024) {
        int idx = base + t;
        int v = (idx < N_NODES) ? g_deg[idx] : 0;
        buf[t] = v;
        __syncthreads();
        for (int o = 1; o < 1024; o <<= 1) {
            int x = (t >= o) ? buf[t - o] : 0;
            __syncthreads();
            buf[t] += x;
            __syncthreads();
        }
        int excl = buf[t] - v;
        if (idx < N_NODES) { g_off[idx] = carry + excl; g_cursor[idx] = carry + excl; }
        int total = buf[1023];
        __syncthreads();
        if (t == 0) carry += total;
        __syncthreads();
    }
    if (t == 0) g_off[N_NODES] = carry;
}

__global__ void k_fill(const int* __restrict__ src, const int* __restrict__ dst) {
    int e = blockIdx.x * blockDim.x + threadIdx.x;
    if (e < N_EDGES) {
        int d = dst[e];
        int p = atomicAdd(&g_cursor[d], 1);
        g_ssrc[p] = src[e];
    }
}

// ---------------- attention scalars ----------------
__global__ void k_dots(const float* __restrict__ att_src, const float* __restrict__ att_dst) {
    int w = (blockIdx.x * blockDim.x + threadIdx.x) >> 5;
    int lane = threadIdx.x & 31;
    if (w >= N_NODES) return;
    const float4* row = (const float4*)(g_h1 + (size_t)w * HID);
    const float4* as4 = (const float4*)att_src;
    const float4* ad4 = (const float4*)att_dst;
    float s = 0.f, d = 0.f;
#pragma unroll
    for (int i = 0; i < 2; i++) {
        float4 h = row[lane + 32 * i];
        float4 a = as4[lane + 32 * i];
        float4 b = ad4[lane + 32 * i];
        s += h.x * a.x + h.y * a.y + h.z * a.z + h.w * a.w;
        d += h.x * b.x + h.y * b.y + h.z * b.z + h.w * b.w;
    }
    for (int o = 16; o; o >>= 1) {
        s += __shfl_xor_sync(0xffffffffu, s, o);
        d += __shfl_xor_sync(0xffffffffu, d, o);
    }
    if (lane == 0) { g_asrc[w] = s; g_adst[w] = d; }
}

__global__ void k_softmax() {
    int w = (blockIdx.x * blockDim.x + threadIdx.x) >> 5;
    int lane = threadIdx.x & 31;
    if (w >= N_NODES) return;
    int lo = g_off[w], hi = g_off[w + 1];
    if (lo == hi) return;
    float ad = g_adst[w];
    float m = -INFINITY;
    for (int p = lo + lane; p < hi; p += 32) {
        float e = g_asrc[g_ssrc[p]] + ad;
        e = e > 0.f ? e : SLOPE * e;
        m = fmaxf(m, e);
    }
    for (int o = 16; o; o >>= 1) m = fmaxf(m, __shfl_xor_sync(0xffffffffu, m, o));
    float sum = 0.f;
    for (int p = lo + lane; p < hi; p += 32) {
        float e = g_asrc[g_ssrc[p]] + ad;
        e = e > 0.f ? e : SLOPE * e;
        float ex = expf(e - m);
        g_alpha[p] = ex;
        sum += ex;
    }
    for (int o = 16; o; o >>= 1) sum += __shfl_xor_sync(0xffffffffu, sum, o);
    float inv = 1.f / sum;
    for (int p = lo + lane; p < hi; p += 32) g_alpha[p] *= inv;
}

// out[n] = act( sum_{p in seg(n)} alpha[p] * h[ssrc[p]] ).  One warp/node, 256 ch.
template <int ACT>
__global__ void k_agg(const float* __restrict__ h, float* __restrict__ out) {
    int w = (blockIdx.x * blockDim.x + threadIdx.x) >> 5;
    int lane = threadIdx.x & 31;
    if (w >= N_NODES) return;
    int lo = g_off[w], hi = g_off[w + 1];
    float4 acc0 = make_float4(0.f, 0.f, 0.f, 0.f);
    float4 acc1 = make_float4(0.f, 0.f, 0.f, 0.f);
    for (int p = lo; p < hi; p++) {
        float a = g_alpha[p];
        const float4* row = (const float4*)(h + (size_t)g_ssrc[p] * HID);
        float4 v0 = row[lane];
        float4 v1 = row[lane + 32];
        acc0.x += a * v0.x; acc0.y += a * v0.y; acc0.z += a * v0.z; acc0.w += a * v0.w;
        acc1.x += a * v1.x; acc1.y += a * v1.y; acc1.z += a * v1.z; acc1.w += a * v1.w;
    }
    float v[8] = {acc0.x, acc0.y, acc0.z, acc0.w, acc1.x, acc1.y, acc1.z, acc1.w};
#pragma unroll
    for (int i = 0; i < 8; i++) {
        if (ACT == 0) v[i] = v[i] > 0.f ? v[i] : (expf(v[i]) - 1.f);
        else          v[i] = v[i] > 0.f ? v[i] : 0.f;
    }
    float4* o4 = (float4*)(out + (size_t)w * HID);
    o4[lane]      = make_float4(v[0], v[1], v[2], v[3]);
    o4[lane + 32] = make_float4(v[4], v[5], v[6], v[7]);
}

// ---------------- TF32 tensor-core GEMM ----------------
// C[M,N] = A[M,K] @ B ;  B row-major [K,N], or [N,K] when TRANSB (=> use B^T).
// BM=128, BN=64, BK=16, 256 threads (8 warps), warp tile 32x32 via m16n8k8 tf32 MMA.
// N % 64 == 0, K % 16 == 0 guaranteed by problem dims; only M guarded.

__device__ __forceinline__ uint32_t f2tf32(float x) {
    uint32_t r;
    asm("cvt.rna.tf32.f32 %0, %1;" : "=r"(r) : "f"(x));
    return r;
}

__device__ __forceinline__ void mma_tf32(float* c, const uint32_t* a, const uint32_t* b) {
    asm volatile(
        "mma.sync.aligned.m16n8k8.row.col.f32.tf32.tf32.f32 "
        "{%0,%1,%2,%3}, {%4,%5,%6,%7}, {%8,%9}, {%0,%1,%2,%3};\n"
        : "+f"(c[0]), "+f"(c[1]), "+f"(c[2]), "+f"(c[3])
        : "r"(a[0]), "r"(a[1]), "r"(a[2]), "r"(a[3]), "r"(b[0]), "r"(b[1]));
}

#define AS_LD 136   // 128 + 8 : stride % 32 == 8 -> conflict-free frag loads
#define BS_LD 72    // 64 + 8

template <bool TRANSB>
__global__ void gemm_tf32(const float* __restrict__ A, const float* __restrict__ B,
                          float* __restrict__ C, int M, int N, int K) {
    __shared__ uint32_t As[16][AS_LD];
    __shared__ uint32_t Bs[16][BS_LD];

    const int t    = threadIdx.x;
    const int lane = t & 31;
    const int warp = t >> 5;
    const int wm   = warp >> 1;         // 0..3 -> M offset 32*wm
    const int wn   = warp & 1;          // 0..1 -> N offset 32*wn
    const int gid  = lane >> 2;         // group id 0..7
    const int tig  = lane & 3;          // thread in group 0..3

    const int mb = blockIdx.y * 128;
    const int nb = blockIdx.x * 64;

    float acc[2][4][4];
#pragma unroll
    for (int i = 0; i < 2; i++)
#pragma unroll
        for (int j = 0; j < 4; j++)
#pragma unroll
            for (int r = 0; r < 4; r++) acc[i][j][r] = 0.f;

    // A-load mapping: 128x16 tile, 2 float4 per thread
    const int am = t >> 1;               // 0..127
    const int aq = (t & 1) * 8;          // 0 or 8 (two float4: k offsets aq, aq+4)
    const bool mok = (mb + am) < M;

    // B-load mapping
    const int bk = t >> 4;               // !TRANSB: 0..15
    const int bn = (t & 15) * 4;
    const int tn = t >> 2;               // TRANSB: 0..63
    const int tk = (t & 3) * 4;

    for (int k0 = 0; k0 < K; k0 += 16) {
        // ---- A: gmem -> tf32 smem (k-major) ----
#pragma unroll
        for (int h = 0; h < 2; h++) {
            int kk = aq + h * 4;
            float4 v = make_float4(0.f, 0.f, 0.f, 0.f);
            if (mok) v = *(const float4*)(A + (size_t)(mb + am) * K + k0 + kk);
            As[kk + 0][am] = f2tf32(v.x);
            As[kk + 1][am] = f2tf32(v.y);
            As[kk + 2][am] = f2tf32(v.z);
            As[kk + 3][am] = f2tf32(v.w);
        }
        // ---- B: gmem -> tf32 smem (k-major) ----
        if (!TRANSB) {
            float4 v = *(const float4*)(B + (size_t)(k0 + bk) * N + nb + bn);
            Bs[bk][bn + 0] = f2tf32(v.x);
            Bs[bk][bn + 1] = f2tf32(v.y);
            Bs[bk][bn + 2] = f2tf32(v.z);
            Bs[bk][bn + 3] = f2tf32(v.w);
        } else {
            float4 v = *(const float4*)(B + (size_t)(nb + tn) * K + k0 + tk);
            Bs[tk + 0][tn] = f2tf32(v.x);
            Bs[tk + 1][tn] = f2tf32(v.y);
            Bs[tk + 2][tn] = f2tf32(v.z);
            Bs[tk + 3][tn] = f2tf32(v.w);
        }
        __syncthreads();

        // ---- compute: 2 k-chunks of 8 ----
#pragma unroll
        for (int kc = 0; kc < 16; kc += 8) {
            uint32_t af[2][4], bf[4][2];
#pragma unroll
            for (int i = 0; i < 2; i++) {
                int row = wm * 32 + i * 16 + gid;
                af[i][0] = As[kc + tig][row];
                af[i][1] = As[kc + tig][row + 8];
                af[i][2] = As[kc + tig + 4][row];
                af[i][3] = As[kc + tig + 4][row + 8];
            }
#pragma unroll
            for (int j = 0; j < 4; j++) {
                int col = wn * 32 + j * 8 + gid;
                bf[j][0] = Bs[kc + tig][col];
                bf[j][1] = Bs[kc + tig + 4][col];
            }
#pragma unroll
            for (int i = 0; i < 2; i++)
#pragma unroll
                for (int j = 0; j < 4; j++)
                    mma_tf32(acc[i][j], af[i], bf[j]);
        }
        __syncthreads();
    }

    // ---- store C ----
#pragma unroll
    for (int i = 0; i < 2; i++) {
        int r0 = mb + wm * 32 + i * 16 + gid;
#pragma unroll
        for (int j = 0; j < 4; j++) {
            int c0 = nb + wn * 32 + j * 8 + tig * 2;
            if (r0 < M)
                *(float2*)(C + (size_t)r0 * N + c0) = make_float2(acc[i][j][0], acc[i][j][1]);
            if (r0 + 8 < M)
                *(float2*)(C + (size_t)(r0 + 8) * N + c0) = make_float2(acc[i][j][2], acc[i][j][3]);
        }
    }
}

// ---------------- launch ----------------
extern "C" void kernel_launch(void* const* d_in, const int* in_sizes, int n_in,
                              void* d_out, int out_size) {
    const float* x        = (const float*)d_in[0];
    const int*   ei       = (const int*)d_in[1];
    const float* W1       = (const float*)d_in[2];
    const float* W2       = (const float*)d_in[3];
    const float* att_src1 = (const float*)d_in[4];
    const float* att_dst1 = (const float*)d_in[5];

    float* latent = (float*)d_out;                               // [N, LAT]
    float* recon  = latent + (size_t)N_NODES * LAT;              // [N, IN_DIM]
    const int* src = ei;
    const int* dst = ei + N_EDGES;

    float *h1, *h1o, *h3, *h3o;
    cudaGetSymbolAddress((void**)&h1,  g_h1);
    cudaGetSymbolAddress((void**)&h1o, g_h1o);
    cudaGetSymbolAddress((void**)&h3,  g_h3);
    cudaGetSymbolAddress((void**)&h3o, g_h3o);

    const int EB = (N_EDGES + 255) / 256;
    const int NB = (N_NODES + 255) / 256;
    const int WB = (N_NODES * 32 + 255) / 256;   // warp-per-node kernels
    const int MT = (N_NODES + 127) / 128;        // gemm M tiles

    // CSR build
    k_zero_deg<<<NB, 256>>>();
    k_count<<<EB, 256>>>(dst);
    k_scan<<<1, 1024>>>();
    k_fill<<<EB, 256>>>(src, dst);

    // encoder GAT1: h1 = x @ W1
    gemm_tf32<false><<<dim3(HID / 64, MT), 256>>>(x, W1, h1, N_NODES, HID, IN_DIM);
    k_dots<<<WB, 256>>>(att_src1, att_dst1);
    k_softmax<<<WB, 256>>>();
    k_agg<0><<<WB, 256>>>(h1, h1o);                              // ELU

    // encoder GAT2: latent = h1o @ W2
    gemm_tf32<false><<<dim3(LAT / 64, MT), 256>>>(h1o, W2, latent, N_NODES, LAT, HID);

    // decoder GAT1: h3 = latent @ W2^T, tied attention, ReLU
    gemm_tf32<true><<<dim3(HID / 64, MT), 256>>>(latent, W2, h3, N_NODES, HID, LAT);
    k_agg<1><<<WB, 256>>>(h3, h3o);                              // ReLU

    // decoder GAT2: recon = h3o @ W1^T
    gemm_tf32<true><<<dim3(IN_DIM / 64, MT), 256>>>(h3o, W1, recon, N_NODES, IN_DIM, HID);
}

// round 3
// speedup vs baseline: 2.4715x; 1.4463x over previous
#include <cuda_runtime.h>
#include <math.h>
#include <stdint.h>

#define N_NODES 50000
#define N_EDGES 800000
#define IN_DIM  512
#define HID     256
#define LAT     64
#define SLOPE   0.2f

// ---------------- scratch (no allocations allowed) ----------------
__device__ float g_h1 [(size_t)N_NODES * HID];
__device__ float g_h1o[(size_t)N_NODES * HID];
__device__ float g_h3 [(size_t)N_NODES * HID];
__device__ float g_h3o[(size_t)N_NODES * HID];
__device__ float g_asrc[N_NODES];
__device__ float g_adst[N_NODES];
__device__ float g_alpha[N_EDGES];     // softmax-normalized attention, CSR order
__device__ int   g_deg[N_NODES];
__device__ int   g_off[N_NODES + 1];
__device__ int   g_cursor[N_NODES];
__device__ int   g_ssrc[N_EDGES];      // src node per CSR-sorted edge
__device__ int   g_bsum[64];           // block sums for parallel scan

// ---------------- CSR build ----------------
__global__ void k_zero_deg() {
    int i = blockIdx.x * blockDim.x + threadIdx.x;
    if (i < N_NODES) g_deg[i] = 0;
}

__global__ void k_count(const int* __restrict__ dst) {
    int e = blockIdx.x * blockDim.x + threadIdx.x;
    if (e < N_EDGES) atomicAdd(&g_deg[dst[e]], 1);
}

// block-local exclusive scan; block sums to g_bsum
__global__ void k_scan1() {
    __shared__ int buf[1024];
    int b = blockIdx.x, t = threadIdx.x;
    int idx = b * 1024 + t;
    int v = (idx < N_NODES) ? g_deg[idx] : 0;
    buf[t] = v;
    __syncthreads();
    for (int o = 1; o < 1024; o <<= 1) {
        int x = (t >= o) ? buf[t - o] : 0;
        __syncthreads();
        buf[t] += x;
        __syncthreads();
    }
    if (idx < N_NODES) g_off[idx] = buf[t] - v;
    if (t == 1023) g_bsum[b] = buf[t];
}

// exclusive scan of up to 64 block sums (1 block, 64 threads)
__global__ void k_scan2(int nblocks) {
    __shared__ int s[64];
    int t = threadIdx.x;
    int v = (t < nblocks) ? g_bsum[t] : 0;
    s[t] = v;
    __syncthreads();
    for (int o = 1; o < 64; o <<= 1) {
        int x = (t >= o) ? s[t - o] : 0;
        __syncthreads();
        s[t] += x;
        __syncthreads();
    }
    g_bsum[t] = s[t] - v;
}

__global__ void k_scan3() {
    int i = blockIdx.x * blockDim.x + threadIdx.x;
    if (i < N_NODES) {
        int o = g_off[i] + g_bsum[i >> 10];
        g_off[i] = o;
        g_cursor[i] = o;
    }
    if (i == 0) g_off[N_NODES] = N_EDGES;
}

__global__ void k_fill(const int* __restrict__ src, const int* __restrict__ dst) {
    int e = blockIdx.x * blockDim.x + threadIdx.x;
    if (e < N_EDGES) {
        int d = dst[e];
        int p = atomicAdd(&g_cursor[d], 1);
        g_ssrc[p] = src[e];
    }
}

// ---------------- attention scalars ----------------
__global__ void k_dots(const float* __restrict__ att_src, const float* __restrict__ att_dst) {
    int w = (blockIdx.x * blockDim.x + threadIdx.x) >> 5;
    int lane = threadIdx.x & 31;
    if (w >= N_NODES) return;
    const float4* row = (const float4*)(g_h1 + (size_t)w * HID);
    const float4* as4 = (const float4*)att_src;
    const float4* ad4 = (const float4*)att_dst;
    float s = 0.f, d = 0.f;
#pragma unroll
    for (int i = 0; i < 2; i++) {
        float4 h = row[lane + 32 * i];
        float4 a = as4[lane + 32 * i];
        float4 b = ad4[lane + 32 * i];
        s += h.x * a.x + h.y * a.y + h.z * a.z + h.w * a.w;
        d += h.x * b.x + h.y * b.y + h.z * b.z + h.w * b.w;
    }
    for (int o = 16; o; o >>= 1) {
        s += __shfl_xor_sync(0xffffffffu, s, o);
        d += __shfl_xor_sync(0xffffffffu, d, o);
    }
    if (lane == 0) { g_asrc[w] = s; g_adst[w] = d; }
}

// ---------------- fused segment softmax + aggregation (encoder) ----------------
// Computes alpha (normalized, stored for reuse by decoder) and out = ELU(sum alpha*h[src]).
__global__ void k_smax_agg_elu(const float* __restrict__ h, float* __restrict__ out) {
    int w = (blockIdx.x * blockDim.x + threadIdx.x) >> 5;
    int lane = threadIdx.x & 31;
    if (w >= N_NODES) return;
    int lo = g_off[w], hi = g_off[w + 1];

    float4 acc0 = make_float4(0.f, 0.f, 0.f, 0.f);
    float4 acc1 = make_float4(0.f, 0.f, 0.f, 0.f);

    if (lo < hi) {
        float ad = g_adst[w];
        float m = -INFINITY;
        for (int p = lo + lane; p < hi; p += 32) {
            float e = g_asrc[g_ssrc[p]] + ad;
            e = e > 0.f ? e : SLOPE * e;
            m = fmaxf(m, e);
        }
        for (int o = 16; o; o >>= 1) m = fmaxf(m, __shfl_xor_sync(0xffffffffu, m, o));
        float sum = 0.f;
        for (int p = lo + lane; p < hi; p += 32) {
            float e = g_asrc[g_ssrc[p]] + ad;
            e = e > 0.f ? e : SLOPE * e;
            float ex = __expf(e - m);
            g_alpha[p] = ex;
            sum += ex;
        }
        for (int o = 16; o; o >>= 1) sum += __shfl_xor_sync(0xffffffffu, sum, o);
        float inv = 1.f / sum;
        for (int p = lo + lane; p < hi; p += 32) g_alpha[p] *= inv;
        __syncwarp();

        // gather with 1-deep prefetch
        int p = lo;
        int sn = g_ssrc[p];
        float an = g_alpha[p];
        const float4* r = (const float4*)(h + (size_t)sn * HID);
        float4 n0 = r[lane], n1 = r[lane + 32];
        while (p < hi) {
            float a = an;
            float4 v0 = n0, v1 = n1;
            ++p;
            if (p < hi) {
                sn = g_ssrc[p];
                an = g_alpha[p];
                r = (const float4*)(h + (size_t)sn * HID);
                n0 = r[lane]; n1 = r[lane + 32];
            }
            acc0.x += a * v0.x; acc0.y += a * v0.y; acc0.z += a * v0.z; acc0.w += a * v0.w;
            acc1.x += a * v1.x; acc1.y += a * v1.y; acc1.z += a * v1.z; acc1.w += a * v1.w;
        }
    }

    float v[8] = {acc0.x, acc0.y, acc0.z, acc0.w, acc1.x, acc1.y, acc1.z, acc1.w};
#pragma unroll
    for (int i = 0; i < 8; i++) v[i] = v[i] > 0.f ? v[i] : (__expf(v[i]) - 1.f);
    float4* o4 = (float4*)(out + (size_t)w * HID);
    o4[lane]      = make_float4(v[0], v[1], v[2], v[3]);
    o4[lane + 32] = make_float4(v[4], v[5], v[6], v[7]);
}

// ---------------- decoder aggregation (reuses alpha), ReLU ----------------
__global__ void k_agg_relu(const float* __restrict__ h, float* __restrict__ out) {
    int w = (blockIdx.x * blockDim.x + threadIdx.x) >> 5;
    int lane = threadIdx.x & 31;
    if (w >= N_NODES) return;
    int lo = g_off[w], hi = g_off[w + 1];
    float4 acc0 = make_float4(0.f, 0.f, 0.f, 0.f);
    float4 acc1 = make_float4(0.f, 0.f, 0.f, 0.f);
    if (lo < hi) {
        int p = lo;
        int sn = g_ssrc[p];
        float an = g_alpha[p];
        const float4* r = (const float4*)(h + (size_t)sn * HID);
        float4 n0 = r[lane], n1 = r[lane + 32];
        while (p < hi) {
            float a = an;
            float4 v0 = n0, v1 = n1;
            ++p;
            if (p < hi) {
                sn = g_ssrc[p];
                an = g_alpha[p];
                r = (const float4*)(h + (size_t)sn * HID);
                n0 = r[lane]; n1 = r[lane + 32];
            }
            acc0.x += a * v0.x; acc0.y += a * v0.y; acc0.z += a * v0.z; acc0.w += a * v0.w;
            acc1.x += a * v1.x; acc1.y += a * v1.y; acc1.z += a * v1.z; acc1.w += a * v1.w;
        }
    }
    float v[8] = {acc0.x, acc0.y, acc0.z, acc0.w, acc1.x, acc1.y, acc1.z, acc1.w};
#pragma unroll
    for (int i = 0; i < 8; i++) v[i] = v[i] > 0.f ? v[i] : 0.f;
    float4* o4 = (float4*)(out + (size_t)w * HID);
    o4[lane]      = make_float4(v[0], v[1], v[2], v[3]);
    o4[lane + 32] = make_float4(v[4], v[5], v[6], v[7]);
}

// ---------------- TF32 tensor-core GEMM, cp.async double-buffered ----------------
// C[M,N] = A[M,K] @ B ;  B row-major [K,N], or [N,K] when TRANSB (uses B^T).
// BM=128, BN=64, BK=16, 256 threads (8 warps), warp tile 32x32 via m16n8k8 tf32 MMA.
// N % 64 == 0, K % 16 == 0; only M guarded.

__device__ __forceinline__ uint32_t f2tf32(float x) {
    uint32_t r;
    asm("cvt.rna.tf32.f32 %0, %1;" : "=r"(r) : "f"(x));
    return r;
}

__device__ __forceinline__ void mma_tf32(float* c, const uint32_t* a, const uint32_t* b) {
    asm volatile(
        "mma.sync.aligned.m16n8k8.row.col.f32.tf32.tf32.f32 "
        "{%0,%1,%2,%3}, {%4,%5,%6,%7}, {%8,%9}, {%0,%1,%2,%3};\n"
        : "+f"(c[0]), "+f"(c[1]), "+f"(c[2]), "+f"(c[3])
        : "r"(a[0]), "r"(a[1]), "r"(a[2]), "r"(a[3]), "r"(b[0]), "r"(b[1]));
}

__device__ __forceinline__ void cp_async16(void* dst, const void* src, bool full) {
    uint32_t d = (uint32_t)__cvta_generic_to_shared(dst);
    int sz = full ? 16 : 0;
    asm volatile("cp.async.cg.shared.global [%0], [%1], 16, %2;\n"
                 :: "r"(d), "l"(src), "r"(sz));
}

#define A_LD  20   // 16 + 4 pad: 20*gid banks form a permutation of 0..31
#define BT_LD 20
#define BN_LD 72   // 64 + 8 pad

template <bool TRANSB>
__global__ void gemm_tf32(const float* __restrict__ A, const float* __restrict__ B,
                          float* __restrict__ C, int M, int N, int K) {
    constexpr int BSZ = TRANSB ? 64 * BT_LD : 16 * BN_LD;
    __shared__ float As[2][128][A_LD];
    __shared__ float Bs[2][BSZ];

    const int t    = threadIdx.x;
    const int lane = t & 31;
    const int warp = t >> 5;
    const int wm   = warp >> 1;
    const int wn   = warp & 1;
    const int gid  = lane >> 2;
    const int tig  = lane & 3;

    const int mb = blockIdx.y * 128;
    const int nb = blockIdx.x * 64;

    float acc[2][4][4];
#pragma unroll
    for (int i = 0; i < 2; i++)
#pragma unroll
        for (int j = 0; j < 4; j++)
#pragma unroll
            for (int r = 0; r < 4; r++) acc[i][j][r] = 0.f;

    auto load_tile = [&](int s, int k0) {
#pragma unroll
        for (int h = 0; h < 2; h++) {
            int idx = t + h * 256;       // 0..511
            int row = idx >> 2;          // 0..127
            int kq  = (idx & 3) * 4;
            cp_async16(&As[s][row][kq],
                       A + (size_t)(mb + row) * K + k0 + kq,
                       (mb + row) < M);
        }
        if (!TRANSB) {
            int kk = t >> 4;             // 0..15
            int nn = (t & 15) * 4;
            cp_async16(&Bs[s][kk * BN_LD + nn],
                       B + (size_t)(k0 + kk) * N + nb + nn, true);
        } else {
            int nn = t >> 2;             // 0..63
            int kq = (t & 3) * 4;
            cp_async16(&Bs[s][nn * BT_LD + kq],
                       B + (size_t)(nb + nn) * K + k0 + kq, true);
        }
        asm volatile("cp.async.commit_group;\n" ::: "memory");
    };

    const int KT = K >> 4;
    load_tile(0, 0);

    for (int kt = 0; kt < KT; kt++) {
        const int s = kt & 1;
        if (kt + 1 < KT) {
            load_tile(s ^ 1, (kt + 1) << 4);
            asm volatile("cp.async.wait_group 1;\n" ::: "memory");
        } else {
            asm volatile("cp.async.wait_group 0;\n" ::: "memory");
        }
        __syncthreads();

#pragma unroll
        for (int kc = 0; kc < 16; kc += 8) {
            uint32_t af[2][4], bf[4][2];
#pragma unroll
            for (int i = 0; i < 2; i++) {
                int row = wm * 32 + i * 16 + gid;
                af[i][0] = f2tf32(As[s][row][kc + tig]);
                af[i][1] = f2tf32(As[s][row + 8][kc + tig]);
                af[i][2] = f2tf32(As[s][row][kc + tig + 4]);
                af[i][3] = f2tf32(As[s][row + 8][kc + tig + 4]);
            }
#pragma unroll
            for (int j = 0; j < 4; j++) {
                int col = wn * 32 + j * 8 + gid;
                if (!TRANSB) {
                    bf[j][0] = f2tf32(Bs[s][(kc + tig) * BN_LD + col]);
                    bf[j][1] = f2tf32(Bs[s][(kc + tig + 4) * BN_LD + col]);
                } else {
                    bf[j][0] = f2tf32(Bs[s][col * BT_LD + kc + tig]);
                    bf[j][1] = f2tf32(Bs[s][col * BT_LD + kc + tig + 4]);
                }
            }
#pragma unroll
            for (int i = 0; i < 2; i++)
#pragma unroll
                for (int j = 0; j < 4; j++)
                    mma_tf32(acc[i][j], af[i], bf[j]);
        }
        __syncthreads();
    }

#pragma unroll
    for (int i = 0; i < 2; i++) {
        int r0 = mb + wm * 32 + i * 16 + gid;
#pragma unroll
        for (int j = 0; j < 4; j++) {
            int c0 = nb + wn * 32 + j * 8 + tig * 2;
            if (r0 < M)
                *(float2*)(C + (size_t)r0 * N + c0) = make_float2(acc[i][j][0], acc[i][j][1]);
            if (r0 + 8 < M)
                *(float2*)(C + (size_t)(r0 + 8) * N + c0) = make_float2(acc[i][j][2], acc[i][j][3]);
        }
    }
}

// ---------------- launch ----------------
extern "C" void kernel_launch(void* const* d_in, const int* in_sizes, int n_in,
                              void* d_out, int out_size) {
    const float* x        = (const float*)d_in[0];
    const int*   ei       = (const int*)d_in[1];
    const float* W1       = (const float*)d_in[2];
    const float* W2       = (const float*)d_in[3];
    const float* att_src1 = (const float*)d_in[4];
    const float* att_dst1 = (const float*)d_in[5];

    float* latent = (float*)d_out;                               // [N, LAT]
    float* recon  = latent + (size_t)N_NODES * LAT;              // [N, IN_DIM]
    const int* src = ei;
    const int* dst = ei + N_EDGES;

    float *h1, *h1o, *h3, *h3o;
    cudaGetSymbolAddress((void**)&h1,  g_h1);
    cudaGetSymbolAddress((void**)&h1o, g_h1o);
    cudaGetSymbolAddress((void**)&h3,  g_h3);
    cudaGetSymbolAddress((void**)&h3o, g_h3o);

    const int EB = (N_EDGES + 255) / 256;
    const int NB = (N_NODES + 255) / 256;
    const int WB = (N_NODES * 32 + 255) / 256;   // warp-per-node kernels
    const int MT = (N_NODES + 127) / 128;        // gemm M tiles
    const int SB = (N_NODES + 1023) / 1024;      // scan blocks (49)

    // CSR build (parallel scan)
    k_zero_deg<<<NB, 256>>>();
    k_count<<<EB, 256>>>(dst);
    k_scan1<<<SB, 1024>>>();
    k_scan2<<<1, 64>>>(SB);
    k_scan3<<<NB, 256>>>();
    k_fill<<<EB, 256>>>(src, dst);

    // encoder GAT1: h1 = x @ W1 ; attention scalars; fused softmax+agg (ELU)
    gemm_tf32<false><<<dim3(HID / 64, MT), 256>>>(x, W1, h1, N_NODES, HID, IN_DIM);
    k_dots<<<WB, 256>>>(att_src1, att_dst1);
    k_smax_agg_elu<<<WB, 256>>>(h1, h1o);

    // encoder GAT2: latent = h1o @ W2
    gemm_tf32<false><<<dim3(LAT / 64, MT), 256>>>(h1o, W2, latent, N_NODES, LAT, HID);

    // decoder GAT1: h3 = latent @ W2^T, tied attention, ReLU
    gemm_tf32<true><<<dim3(HID / 64, MT), 256>>>(latent, W2, h3, N_NODES, HID, LAT);
    k_agg_relu<<<WB, 256>>>(h3, h3o);

    // decoder GAT2: recon = h3o @ W1^T
    gemm_tf32<true><<<dim3(IN_DIM / 64, MT), 256>>>(h3o, W1, recon, N_NODES, IN_DIM, HID);
}

// round 4
// speedup vs baseline: 2.5338x; 1.0252x over previous
#include <cuda_runtime.h>
#include <math.h>
#include <stdint.h>

#define N_NODES 50000
#define N_EDGES 800000
#define IN_DIM  512
#define HID     256
#define LAT     64
#define SLOPE   0.2f

// ---------------- scratch (no allocations allowed) ----------------
__device__ float g_h1 [(size_t)N_NODES * HID];
__device__ float g_h1o[(size_t)N_NODES * HID];
__device__ float g_h3 [(size_t)N_NODES * HID];
__device__ float g_h3o[(size_t)N_NODES * HID];
__device__ float g_asrc[N_NODES];
__device__ float g_adst[N_NODES];
__device__ float g_inv [N_NODES];      // 1/denominator per dst node
__device__ float g_alpha[N_EDGES];     // UNNORMALIZED exp(leakyrelu(e)), CSR order
__device__ int   g_deg[N_NODES];
__device__ int   g_off[N_NODES + 1];
__device__ int   g_cursor[N_NODES];
__device__ int   g_ssrc[N_EDGES];      // src node per CSR-sorted edge
__device__ int   g_bsum[64];           // block sums for parallel scan

// ---------------- CSR build ----------------
__global__ void k_zero() {
    int i = blockIdx.x * blockDim.x + threadIdx.x;
    if (i < N_NODES) { g_deg[i] = 0; g_asrc[i] = 0.f; g_adst[i] = 0.f; }
}

__global__ void k_count(const int* __restrict__ dst) {
    int e = blockIdx.x * blockDim.x + threadIdx.x;
    if (e < N_EDGES) atomicAdd(&g_deg[dst[e]], 1);
}

__global__ void k_scan1() {
    __shared__ int buf[1024];
    int b = blockIdx.x, t = threadIdx.x;
    int idx = b * 1024 + t;
    int v = (idx < N_NODES) ? g_deg[idx] : 0;
    buf[t] = v;
    __syncthreads();
    for (int o = 1; o < 1024; o <<= 1) {
        int x = (t >= o) ? buf[t - o] : 0;
        __syncthreads();
        buf[t] += x;
        __syncthreads();
    }
    if (idx < N_NODES) g_off[idx] = buf[t] - v;
    if (t == 1023) g_bsum[b] = buf[t];
}

__global__ void k_scan2(int nblocks) {
    __shared__ int s[64];
    int t = threadIdx.x;
    int v = (t < nblocks) ? g_bsum[t] : 0;
    s[t] = v;
    __syncthreads();
    for (int o = 1; o < 64; o <<= 1) {
        int x = (t >= o) ? s[t - o] : 0;
        __syncthreads();
        s[t] += x;
        __syncthreads();
    }
    g_bsum[t] = s[t] - v;
}

__global__ void k_scan3() {
    int i = blockIdx.x * blockDim.x + threadIdx.x;
    if (i < N_NODES) {
        int o = g_off[i] + g_bsum[i >> 10];
        g_off[i] = o;
        g_cursor[i] = o;
    }
    if (i == 0) g_off[N_NODES] = N_EDGES;
}

__global__ void k_fill(const int* __restrict__ src, const int* __restrict__ dst) {
    int e = blockIdx.x * blockDim.x + threadIdx.x;
    if (e < N_EDGES) {
        int d = dst[e];
        int p = atomicAdd(&g_cursor[d], 1);
        g_ssrc[p] = src[e];
    }
}

// ---------------- fused segment softmax + aggregation (encoder, ELU) --------
// Pass A (lane-strided): ex = exp(leakyrelu(asrc[src]+adst[dst])) -> g_alpha, sum
// Pass B (warp gather):  acc = sum ex * h[src];  out = ELU(acc / sum)
__global__ void k_smax_agg_elu(const float* __restrict__ h, float* __restrict__ out) {
    int w = (blockIdx.x * blockDim.x + threadIdx.x) >> 5;
    int lane = threadIdx.x & 31;
    if (w >= N_NODES) return;
    int lo = g_off[w], hi = g_off[w + 1];

    float4 acc0 = make_float4(0.f, 0.f, 0.f, 0.f);
    float4 acc1 = make_float4(0.f, 0.f, 0.f, 0.f);
    float inv = 0.f;

    if (lo < hi) {
        float ad = g_adst[w];
        float sum = 0.f;
        for (int p = lo + lane; p < hi; p += 32) {
            float e = g_asrc[g_ssrc[p]] + ad;
            e = e > 0.f ? e : SLOPE * e;
            float ex = __expf(e);
            g_alpha[p] = ex;
            sum += ex;
        }
        for (int o = 16; o; o >>= 1) sum += __shfl_xor_sync(0xffffffffu, sum, o);
        inv = 1.f / sum;
        if (lane == 0) g_inv[w] = inv;
        __syncwarp();

        int p = lo;
        int sn = g_ssrc[p];
        float an = g_alpha[p];
        const float4* r = (const float4*)(h + (size_t)sn * HID);
        float4 n0 = r[lane], n1 = r[lane + 32];
        while (p < hi) {
            float a = an;
            float4 v0 = n0, v1 = n1;
            ++p;
            if (p < hi) {
                sn = g_ssrc[p];
                an = g_alpha[p];
                r = (const float4*)(h + (size_t)sn * HID);
                n0 = r[lane]; n1 = r[lane + 32];
            }
            acc0.x += a * v0.x; acc0.y += a * v0.y; acc0.z += a * v0.z; acc0.w += a * v0.w;
            acc1.x += a * v1.x; acc1.y += a * v1.y; acc1.z += a * v1.z; acc1.w += a * v1.w;
        }
    }

    float v[8] = {acc0.x, acc0.y, acc0.z, acc0.w, acc1.x, acc1.y, acc1.z, acc1.w};
#pragma unroll
    for (int i = 0; i < 8; i++) {
        v[i] *= inv;
        v[i] = v[i] > 0.f ? v[i] : (__expf(v[i]) - 1.f);
    }
    float4* o4 = (float4*)(out + (size_t)w * HID);
    o4[lane]      = make_float4(v[0], v[1], v[2], v[3]);
    o4[lane + 32] = make_float4(v[4], v[5], v[6], v[7]);
}

// ---------------- decoder aggregation (reuses alpha & inv), ReLU ------------
__global__ void k_agg_relu(const float* __restrict__ h, float* __restrict__ out) {
    int w = (blockIdx.x * blockDim.x + threadIdx.x) >> 5;
    int lane = threadIdx.x & 31;
    if (w >= N_NODES) return;
    int lo = g_off[w], hi = g_off[w + 1];
    float4 acc0 = make_float4(0.f, 0.f, 0.f, 0.f);
    float4 acc1 = make_float4(0.f, 0.f, 0.f, 0.f);
    float inv = 0.f;
    if (lo < hi) {
        inv = g_inv[w];
        int p = lo;
        int sn = g_ssrc[p];
        float an = g_alpha[p];
        const float4* r = (const float4*)(h + (size_t)sn * HID);
        float4 n0 = r[lane], n1 = r[lane + 32];
        while (p < hi) {
            float a = an;
            float4 v0 = n0, v1 = n1;
            ++p;
            if (p < hi) {
                sn = g_ssrc[p];
                an = g_alpha[p];
                r = (const float4*)(h + (size_t)sn * HID);
                n0 = r[lane]; n1 = r[lane + 32];
            }
            acc0.x += a * v0.x; acc0.y += a * v0.y; acc0.z += a * v0.z; acc0.w += a * v0.w;
            acc1.x += a * v1.x; acc1.y += a * v1.y; acc1.z += a * v1.z; acc1.w += a * v1.w;
        }
    }
    float v[8] = {acc0.x, acc0.y, acc0.z, acc0.w, acc1.x, acc1.y, acc1.z, acc1.w};
#pragma unroll
    for (int i = 0; i < 8; i++) {
        v[i] *= inv;
        v[i] = v[i] > 0.f ? v[i] : 0.f;
    }
    float4* o4 = (float4*)(out + (size_t)w * HID);
    o4[lane]      = make_float4(v[0], v[1], v[2], v[3]);
    o4[lane + 32] = make_float4(v[4], v[5], v[6], v[7]);
}

// ---------------- TF32 tensor-core GEMM, cp.async double-buffered ----------------
// C[M,N] = A[M,K] @ B ;  B row-major [K,N], or [N,K] when TRANSB (uses B^T).
// BM=128, BN in {64,128}, BK=16, 256 threads (8 warps), warp tile 32 x BN/2.
// If EPI: also atomicAdd per-row dots with att_src/att_dst into g_asrc/g_adst.
// N % BN == 0, K % 16 == 0; only M guarded.

__device__ __forceinline__ uint32_t f2tf32(float x) {
    uint32_t r;
    asm("cvt.rna.tf32.f32 %0, %1;" : "=r"(r) : "f"(x));
    return r;
}

__device__ __forceinline__ void mma_tf32(float* c, const uint32_t* a, const uint32_t* b) {
    asm volatile(
        "mma.sync.aligned.m16n8k8.row.col.f32.tf32.tf32.f32 "
        "{%0,%1,%2,%3}, {%4,%5,%6,%7}, {%8,%9}, {%0,%1,%2,%3};\n"
        : "+f"(c[0]), "+f"(c[1]), "+f"(c[2]), "+f"(c[3])
        : "r"(a[0]), "r"(a[1]), "r"(a[2]), "r"(a[3]), "r"(b[0]), "r"(b[1]));
}

__device__ __forceinline__ void cp_async16(void* dst, const void* src, bool full) {
    uint32_t d = (uint32_t)__cvta_generic_to_shared(dst);
    int sz = full ? 16 : 0;
    asm volatile("cp.async.cg.shared.global [%0], [%1], 16, %2;\n"
                 :: "r"(d), "l"(src), "r"(sz));
}

#define A_LD 20   // 16 + 4 pad: banks 20*gid+tig form a permutation of 0..31

template <bool TRANSB, int BN, bool EPI>
__global__ __launch_bounds__(256, 2)
void gemm_tf32(const float* __restrict__ A, const float* __restrict__ B,
               float* __restrict__ C, int M, int N, int K,
               const float* __restrict__ attS, const float* __restrict__ attD) {
    constexpr int NF  = BN / 16;                    // n-fragments per warp
    constexpr int BLD = BN + 8;                     // padded row for k-major B
    constexpr int BSZ = TRANSB ? BN * A_LD : 16 * BLD;
    __shared__ float As[2][128][A_LD];
    __shared__ float Bs[2][BSZ];

    const int t    = threadIdx.x;
    const int lane = t & 31;
    const int warp = t >> 5;
    const int wm   = warp >> 1;                     // 0..3 -> M offset 32*wm
    const int wn   = warp & 1;                      // 0..1 -> N offset (BN/2)*wn
    const int gid  = lane >> 2;
    const int tig  = lane & 3;

    const int mb = blockIdx.y * 128;
    const int nb = blockIdx.x * BN;

    float acc[2][NF][4];
#pragma unroll
    for (int i = 0; i < 2; i++)
#pragma unroll
        for (int j = 0; j < NF; j++)
#pragma unroll
            for (int r = 0; r < 4; r++) acc[i][j][r] = 0.f;

    auto load_tile = [&](int s, int k0) {
#pragma unroll
        for (int h = 0; h < 2; h++) {
            int idx = t + h * 256;
            int row = idx >> 2;
            int kq  = (idx & 3) * 4;
            cp_async16(&As[s][row][kq],
                       A + (size_t)(mb + row) * K + k0 + kq,
                       (mb + row) < M);
        }
        if (!TRANSB) {
            // 16 x BN tile: BN=64 -> 1 float4/thread, BN=128 -> 2
#pragma unroll
            for (int h = 0; h < BN / 64; h++) {
                int idx = t + h * 256;              // 0 .. 16*BN/4-1
                int kk  = idx / (BN / 4);
                int nn  = (idx % (BN / 4)) * 4;
                cp_async16(&Bs[s][kk * BLD + nn],
                           B + (size_t)(k0 + kk) * N + nb + nn, true);
            }
        } else {
            // BN x 16 tile of B[N,K]
#pragma unroll
            for (int h = 0; h < BN / 64; h++) {
                int idx = t + h * 256;
                int nn  = idx >> 2;
                int kq  = (idx & 3) * 4;
                cp_async16(&Bs[s][nn * A_LD + kq],
                           B + (size_t)(nb + nn) * K + k0 + kq, true);
            }
        }
        asm volatile("cp.async.commit_group;\n" ::: "memory");
    };

    const int KT = K >> 4;
    load_tile(0, 0);

    for (int kt = 0; kt < KT; kt++) {
        const int s = kt & 1;
        if (kt + 1 < KT) {
            load_tile(s ^ 1, (kt + 1) << 4);
            asm volatile("cp.async.wait_group 1;\n" ::: "memory");
        } else {
            asm volatile("cp.async.wait_group 0;\n" ::: "memory");
        }
        __syncthreads();

#pragma unroll
        for (int kc = 0; kc < 16; kc += 8) {
            uint32_t af[2][4], bf[NF][2];
#pragma unroll
            for (int i = 0; i < 2; i++) {
                int row = wm * 32 + i * 16 + gid;
                af[i][0] = f2tf32(As[s][row][kc + tig]);
                af[i][1] = f2tf32(As[s][row + 8][kc + tig]);
                af[i][2] = f2tf32(As[s][row][kc + tig + 4]);
                af[i][3] = f2tf32(As[s][row + 8][kc + tig + 4]);
            }
#pragma unroll
            for (int j = 0; j < NF; j++) {
                int col = wn * (BN / 2) + j * 8 + gid;
                if (!TRANSB) {
                    bf[j][0] = f2tf32(Bs[s][(kc + tig) * BLD + col]);
                    bf[j][1] = f2tf32(Bs[s][(kc + tig + 4) * BLD + col]);
                } else {
                    bf[j][0] = f2tf32(Bs[s][col * A_LD + kc + tig]);
                    bf[j][1] = f2tf32(Bs[s][col * A_LD + kc + tig + 4]);
                }
            }
#pragma unroll
            for (int i = 0; i < 2; i++)
#pragma unroll
                for (int j = 0; j < NF; j++)
                    mma_tf32(acc[i][j], af[i], bf[j]);
        }
        __syncthreads();
    }

    // ---- store C ----
#pragma unroll
    for (int i = 0; i < 2; i++) {
        int r0 = mb + wm * 32 + i * 16 + gid;
#pragma unroll
        for (int j = 0; j < NF; j++) {
            int c0 = nb + wn * (BN / 2) + j * 8 + tig * 2;
            if (r0 < M)
                *(float2*)(C + (size_t)r0 * N + c0) = make_float2(acc[i][j][0], acc[i][j][1]);
            if (r0 + 8 < M)
                *(float2*)(C + (size_t)(r0 + 8) * N + c0) = make_float2(acc[i][j][2], acc[i][j][3]);
        }
    }

    // ---- fused attention-dot epilogue (gemm1 only) ----
    if (EPI) {
#pragma unroll
        for (int i = 0; i < 2; i++) {
            float ps = 0.f, pd = 0.f, ps8 = 0.f, pd8 = 0.f;
#pragma unroll
            for (int j = 0; j < NF; j++) {
                int c0 = nb + wn * (BN / 2) + j * 8 + tig * 2;
                float sa = __ldg(attS + c0), sb = __ldg(attS + c0 + 1);
                float da = __ldg(attD + c0), db = __ldg(attD + c0 + 1);
                ps  += acc[i][j][0] * sa + acc[i][j][1] * sb;
                pd  += acc[i][j][0] * da + acc[i][j][1] * db;
                ps8 += acc[i][j][2] * sa + acc[i][j][3] * sb;
                pd8 += acc[i][j][2] * da + acc[i][j][3] * db;
            }
#pragma unroll
            for (int o = 1; o <= 2; o <<= 1) {
                ps  += __shfl_xor_sync(0xffffffffu, ps,  o);
                pd  += __shfl_xor_sync(0xffffffffu, pd,  o);
                ps8 += __shfl_xor_sync(0xffffffffu, ps8, o);
                pd8 += __shfl_xor_sync(0xffffffffu, pd8, o);
            }
            if (tig == 0) {
                int r0 = mb + wm * 32 + i * 16 + gid;
                if (r0 < M)     { atomicAdd(&g_asrc[r0], ps);      atomicAdd(&g_adst[r0], pd); }
                if (r0 + 8 < M) { atomicAdd(&g_asrc[r0 + 8], ps8); atomicAdd(&g_adst[r0 + 8], pd8); }
            }
        }
    }
}

// ---------------- launch ----------------
extern "C" void kernel_launch(void* const* d_in, const int* in_sizes, int n_in,
                              void* d_out, int out_size) {
    const float* x        = (const float*)d_in[0];
    const int*   ei       = (const int*)d_in[1];
    const float* W1       = (const float*)d_in[2];
    const float* W2       = (const float*)d_in[3];
    const float* att_src1 = (const float*)d_in[4];
    const float* att_dst1 = (const float*)d_in[5];

    float* latent = (float*)d_out;                               // [N, LAT]
    float* recon  = latent + (size_t)N_NODES * LAT;              // [N, IN_DIM]
    const int* src = ei;
    const int* dst = ei + N_EDGES;

    float *h1, *h1o, *h3, *h3o;
    cudaGetSymbolAddress((void**)&h1,  g_h1);
    cudaGetSymbolAddress((void**)&h1o, g_h1o);
    cudaGetSymbolAddress((void**)&h3,  g_h3);
    cudaGetSymbolAddress((void**)&h3o, g_h3o);

    const int EB = (N_EDGES + 255) / 256;
    const int NB = (N_NODES + 255) / 256;
    const int WB = (N_NODES * 32 + 255) / 256;   // warp-per-node kernels
    const int MT = (N_NODES + 127) / 128;        // gemm M tiles
    const int SB = (N_NODES + 1023) / 1024;      // scan blocks (49)

    // CSR build (parallel scan) + zero attention accumulators
    k_zero<<<NB, 256>>>();
    k_count<<<EB, 256>>>(dst);
    k_scan1<<<SB, 1024>>>();
    k_scan2<<<1, 64>>>(SB);
    k_scan3<<<NB, 256>>>();
    k_fill<<<EB, 256>>>(src, dst);

    // encoder GAT1: h1 = x @ W1 with fused att-dot epilogue; fused softmax+agg (ELU)
    gemm_tf32<false, 128, true><<<dim3(HID / 128, MT), 256>>>(
        x, W1, h1, N_NODES, HID, IN_DIM, att_src1, att_dst1);
    k_smax_agg_elu<<<WB, 256>>>(h1, h1o);

    // encoder GAT2: latent = h1o @ W2
    gemm_tf32<false, 64, false><<<dim3(LAT / 64, MT), 256>>>(
        h1o, W2, latent, N_NODES, LAT, HID, nullptr, nullptr);

    // decoder GAT1: h3 = latent @ W2^T, tied attention, ReLU
    gemm_tf32<true, 128, false><<<dim3(HID / 128, MT), 256>>>(
        latent, W2, h3, N_NODES, HID, LAT, nullptr, nullptr);
    k_agg_relu<<<WB, 256>>>(h3, h3o);

    // decoder GAT2: recon = h3o @ W1^T
    gemm_tf32<true, 128, false><<<dim3(IN_DIM / 128, MT), 256>>>(
        h3o, W1, recon, N_NODES, IN_DIM, HID, nullptr, nullptr);
}